// round 4
// baseline (speedup 1.0000x reference)
#include <cuda_runtime.h>
#include <cstdint>

// YOLO loss, traffic-minimized direct-LDG gather.
// Key insight: HBM fetches 32B sectors. noobj cells (70%) need only
// preds ch0/ch5 and target ch0 -> skip ~55MB of the 176.6MB by branching
// on the object mask BEFORE loading the rest. Predicated-off LDGs fetch
// nothing. ~121MB effective traffic -> ~20us DRAM floor.

#define PRED_CH 30
#define TGT_CH 25
#define LAMBDA_COORD 5.0f
#define LAMBDA_NOOBJ 0.5f

#define BLOCK 256
#define NCELLS 802816            // 16384*7*7 (asserted via in_sizes at launch)
#define NBLOCKS (NCELLS / BLOCK) // 3136 exact

__device__ float g_partials[NBLOCKS];

__global__ __launch_bounds__(BLOCK)
void yolo_gather_kernel(const float* __restrict__ preds,
                        const float* __restrict__ targets,
                        int ncells) {
    const int tid = threadIdx.x;
    const int cell = blockIdx.x * BLOCK + tid;

    float loss = 0.0f;
    if (cell < ncells) {
        const float* __restrict__ t = targets + (size_t)cell * TGT_CH;
        const float* __restrict__ p = preds + (size_t)cell * PRED_CH;

        const float c  = __ldg(t + 0);
        const float s0 = __ldg(p + 0);
        const float s1 = __ldg(p + 5);

        if (c == 1.0f) {
            const int off = (s1 > s0) ? 5 : 0;   // argmax, first-max tiebreak
            const float pc = (off ? s1 : s0);

            // box loss (4 scalar loads from each side)
            float box_loss = 0.0f;
            #pragma unroll
            for (int k = 1; k < 5; k++) {
                const float d = __ldg(p + off + k) - __ldg(t + k);
                box_loss = fmaf(d, d, box_loss);
            }
            const float dpc = pc - 1.0f;         // t[0] == 1 exactly

            // class loss: p[10..29] is 8B-aligned (cell*120+40) -> float2
            float class_loss = 0.0f;
            const float2* __restrict__ pc2 = reinterpret_cast<const float2*>(p + 10);
            #pragma unroll
            for (int j = 0; j < 10; j++) {
                const float2 pv = __ldg(pc2 + j);
                const float d0 = pv.x - __ldg(t + 5 + 2 * j);
                const float d1 = pv.y - __ldg(t + 6 + 2 * j);
                class_loss = fmaf(d0, d0, fmaf(d1, d1, class_loss));
            }
            loss = fmaf(LAMBDA_COORD, box_loss, fmaf(dpc, dpc, class_loss));
        } else {
            loss = LAMBDA_NOOBJ * fmaf(s0, s0, s1 * s1);
        }
    }

    // warp reduce
    #pragma unroll
    for (int o = 16; o > 0; o >>= 1)
        loss += __shfl_xor_sync(0xffffffffu, loss, o);

    __shared__ float wsum[BLOCK / 32];
    if ((tid & 31) == 0) wsum[tid >> 5] = loss;
    __syncthreads();

    if (tid < 32) {
        float v = (tid < BLOCK / 32) ? wsum[tid] : 0.0f;
        #pragma unroll
        for (int o = (BLOCK / 64); o > 0; o >>= 1)
            v += __shfl_xor_sync(0xffffffffu, v, o);
        if (tid == 0) g_partials[blockIdx.x] = v;
    }
}

__global__ __launch_bounds__(1024)
void yolo_finalize_kernel(float* __restrict__ out, int nparts) {
    const int tid = threadIdx.x;
    float v = 0.0f;
    for (int i = tid; i < nparts; i += 1024)
        v += g_partials[i];
    #pragma unroll
    for (int o = 16; o > 0; o >>= 1)
        v += __shfl_xor_sync(0xffffffffu, v, o);

    __shared__ float wsum[32];
    if ((tid & 31) == 0) wsum[tid >> 5] = v;
    __syncthreads();
    if (tid < 32) {
        float s = wsum[tid];
        #pragma unroll
        for (int o = 16; o > 0; o >>= 1)
            s += __shfl_xor_sync(0xffffffffu, s, o);
        if (tid == 0) out[0] = s;
    }
}

extern "C" void kernel_launch(void* const* d_in, const int* in_sizes, int n_in,
                              void* d_out, int out_size) {
    const float* preds   = (const float*)d_in[0];
    const float* targets = (const float*)d_in[1];
    float* out = (float*)d_out;

    const int ncells = in_sizes[0] / PRED_CH;          // 802816
    const int nblocks = (ncells + BLOCK - 1) / BLOCK;  // 3136

    yolo_gather_kernel<<<nblocks, BLOCK>>>(preds, targets, ncells);
    yolo_finalize_kernel<<<1, 1024>>>(out, nblocks);
}

// round 5
// speedup vs baseline: 1.1846x; 1.1846x over previous
#include <cuda_runtime.h>
#include <cstdint>

// YOLO loss: persistent cp.async 3-stage pipeline (R2 config) with
// issue-before-compute (single barrier per tile) and fused last-block
// finalize (one kernel launch total).
// preds:   [802816 x 30] f32, targets: [802816 x 25] f32 -> scalar.

#define THREADS 64
#define TILE 64
#define STAGES 3
#define PRED_F4 (TILE * 30 / 4)        // 480
#define TGT_F4  (TILE * 25 / 4)        // 400
#define STAGE_FLOATS (TILE * 55)       // 14080 B per stage
#define GRID 760                       // 5 blocks/SM persistent

#define LAMBDA_COORD 5.0f
#define LAMBDA_NOOBJ 0.5f

__device__ float g_partials[GRID];
__device__ int   g_counter = 0;

__device__ __forceinline__ void cp16(uint32_t smem_addr, const float4* gptr) {
    asm volatile("cp.async.cg.shared.global [%0], [%1], 16;"
                 :: "r"(smem_addr), "l"(gptr));
}

__global__ __launch_bounds__(THREADS)
void yolo_loss_kernel(const float* __restrict__ preds,
                      const float* __restrict__ targets,
                      float* __restrict__ out,
                      int ntiles) {
    __shared__ float buf[STAGES * STAGE_FLOATS];   // 42240 B
    __shared__ float wsum[THREADS / 32];

    const int tid = threadIdx.x;
    const int grid = gridDim.x;
    const uint32_t sbase = (uint32_t)__cvta_generic_to_shared(buf);

    auto issue = [&](int tile, int stage) {
        if (tile < ntiles) {
            const float4* pg = reinterpret_cast<const float4*>(preds)
                               + (size_t)tile * PRED_F4;
            const uint32_t sp = sbase + (uint32_t)stage * (STAGE_FLOATS * 4);
            for (int idx = tid; idx < PRED_F4; idx += THREADS)
                cp16(sp + idx * 16, pg + idx);
            const float4* tg = reinterpret_cast<const float4*>(targets)
                               + (size_t)tile * TGT_F4;
            const uint32_t st = sp + TILE * 30 * 4;
            for (int idx = tid; idx < TGT_F4; idx += THREADS)
                cp16(st + idx * 16, tg + idx);
        }
        asm volatile("cp.async.commit_group;");    // uniform group counting
    };

    const int t0 = (int)blockIdx.x;
    issue(t0, 0);
    issue(t0 + grid, 1);

    float acc = 0.0f;
    int i = 0;
    for (int t = t0; t < ntiles; t += grid, i++) {
        const int stage = i % STAGES;

        asm volatile("cp.async.wait_group 1;");    // group i complete
        __syncthreads();   // also proves all threads done with stage (i+2)%3

        // Refill the stage consumed at iter i-1, BEFORE compute: keeps two
        // groups in flight through the compute phase. No second barrier —
        // the next iteration's syncthreads provides the consume->overwrite
        // ordering.
        issue(t + 2 * grid, (i + 2) % STAGES);

        const float* p  = buf + stage * STAGE_FLOATS + tid * 30;
        const float* tg = buf + stage * STAGE_FLOATS + TILE * 30 + tid * 25;

        const float s0 = p[0];
        const float s1 = p[5];
        const int off = (s1 > s0) ? 5 : 0;   // argmax, first-max tiebreak

        float loss;
        if (tg[0] == 1.0f) {
            float box_loss = 0.0f;
            #pragma unroll
            for (int k = 1; k < 5; k++) {
                const float d = p[off + k] - tg[k];
                box_loss = fmaf(d, d, box_loss);
            }
            const float dpc = p[off] - 1.0f;   // tg[0] == 1 exactly
            float class_loss = 0.0f;
            #pragma unroll
            for (int j = 0; j < 20; j++) {
                const float d = p[10 + j] - tg[5 + j];
                class_loss = fmaf(d, d, class_loss);
            }
            loss = fmaf(LAMBDA_COORD, box_loss, fmaf(dpc, dpc, class_loss));
        } else {
            loss = LAMBDA_NOOBJ * (s0 * s0 + s1 * s1);
        }
        acc += loss;
    }

    asm volatile("cp.async.wait_group 0;");    // drain tails

    // Block reduce -> per-block partial.
    #pragma unroll
    for (int o = 16; o > 0; o >>= 1)
        acc += __shfl_xor_sync(0xffffffffu, acc, o);
    if ((tid & 31) == 0) wsum[tid >> 5] = acc;
    __syncthreads();

    __shared__ int is_last;
    if (tid == 0) {
        g_partials[blockIdx.x] = wsum[0] + wsum[1];
        __threadfence();
        is_last = (atomicAdd(&g_counter, 1) == grid - 1);
    }
    __syncthreads();

    // Last block to finish reduces all partials and writes the scalar.
    if (is_last) {
        __threadfence();
        float v = 0.0f;
        for (int idx = tid; idx < grid; idx += THREADS)
            v += g_partials[idx];
        #pragma unroll
        for (int o = 16; o > 0; o >>= 1)
            v += __shfl_xor_sync(0xffffffffu, v, o);
        if ((tid & 31) == 0) wsum[tid >> 5] = v;
        __syncthreads();
        if (tid == 0) {
            out[0] = wsum[0] + wsum[1];
            g_counter = 0;             // reset for next graph replay
        }
    }
}

extern "C" void kernel_launch(void* const* d_in, const int* in_sizes, int n_in,
                              void* d_out, int out_size) {
    const float* preds   = (const float*)d_in[0];
    const float* targets = (const float*)d_in[1];
    float* out = (float*)d_out;

    const int ncells = in_sizes[0] / 30;       // 802816
    const int ntiles = ncells / TILE;          // 12544

    yolo_loss_kernel<<<GRID, THREADS>>>(preds, targets, out, ntiles);
}